// round 8
// baseline (speedup 1.0000x reference)
#include <cuda_runtime.h>
#include <cuda_fp16.h>

#define NPTS  32768
#define BATCH 8
#define CH    128
#define RES   32
#define R3    32768   // 32^3

// Scratch (device globals: no allocation allowed)
__device__ __half g_gridh[(size_t)BATCH * R3 * CH];   // fp16 scatter sums [b][v][c] (64 MB)
__device__ float  g_cnt  [BATCH * R3];
__device__ float  g_sum  [2][BATCH][3];               // mean partials (atomicAdd)
__device__ int    g_max  [2][BATCH];                  // max ||c-mean||^2 as int bits

// ---------------------------------------------------------------------------
// Zero fp16 grid + counts + stat accumulators (graph replays -> every launch)
// ---------------------------------------------------------------------------
__global__ void zero_kernel() {
    const size_t gtotal = (size_t)BATCH * R3 * CH * 2 / 16;   // 4M float4
    float4* p = (float4*)g_gridh;
    size_t stride = (size_t)gridDim.x * blockDim.x;
    for (size_t i = (size_t)blockIdx.x * blockDim.x + threadIdx.x; i < gtotal; i += stride)
        p[i] = make_float4(0.f, 0.f, 0.f, 0.f);
    const size_t ctotal = (size_t)BATCH * R3 / 4;
    float4* q = (float4*)g_cnt;
    for (size_t i = (size_t)blockIdx.x * blockDim.x + threadIdx.x; i < ctotal; i += stride)
        q[i] = make_float4(0.f, 0.f, 0.f, 0.f);
    if (blockIdx.x == 0 && threadIdx.x < 64) {
        if (threadIdx.x < 48) ((float*)g_sum)[threadIdx.x] = 0.f;
        else                  ((int*)g_max)[threadIdx.x - 48] = 0;
    }
}

// ---------------------------------------------------------------------------
// Independent x1 -> out[:, 0:128, :] passthrough copy (flat float4 stream)
// ---------------------------------------------------------------------------
__global__ void copy_kernel(const float* __restrict__ x1f, float* __restrict__ out) {
    const float4* src = (const float4*)x1f;
    const size_t nvec = (size_t)BATCH * CH * NPTS / 4;   // 16M float4
    size_t stride = (size_t)gridDim.x * blockDim.x;
    for (size_t i = (size_t)blockIdx.x * blockDim.x + threadIdx.x; i < nvec; i += stride) {
        size_t e = i * 4;
        size_t bb = e >> 22;                              // CH*NPTS = 2^22
        float4 v = __ldcs(&src[i]);
        __stcs((float4*)(out + e + (bb << 22)), v);
    }
}

// ---------------------------------------------------------------------------
// Mean partials: 128 blocks (2 tensors x 8 batches x 8 chunks)
// ---------------------------------------------------------------------------
__global__ void mean_kernel(const float* __restrict__ c1, const float* __restrict__ c2) {
    int id = blockIdx.x;
    int t = id >> 6, b = (id >> 3) & 7, s = id & 7;
    const float* c = (t ? c2 : c1) + (size_t)b * 3 * NPTS + s * 4096;

    float s0 = 0.f, s1 = 0.f, s2 = 0.f;
    for (int n = threadIdx.x; n < 4096; n += 256) {
        s0 += c[n]; s1 += c[NPTS + n]; s2 += c[2 * NPTS + n];
    }
    #pragma unroll
    for (int off = 16; off; off >>= 1) {
        s0 += __shfl_down_sync(0xffffffffu, s0, off);
        s1 += __shfl_down_sync(0xffffffffu, s1, off);
        s2 += __shfl_down_sync(0xffffffffu, s2, off);
    }
    __shared__ float red[3][8];
    int lane = threadIdx.x & 31, w = threadIdx.x >> 5;
    if (lane == 0) { red[0][w] = s0; red[1][w] = s1; red[2][w] = s2; }
    __syncthreads();
    if (threadIdx.x == 0) {
        float m0 = 0.f, m1 = 0.f, m2 = 0.f;
        #pragma unroll
        for (int i = 0; i < 8; i++) { m0 += red[0][i]; m1 += red[1][i]; m2 += red[2][i]; }
        atomicAdd(&g_sum[t][b][0], m0);
        atomicAdd(&g_sum[t][b][1], m1);
        atomicAdd(&g_sum[t][b][2], m2);
    }
}

// ---------------------------------------------------------------------------
// Max ||c - mean||^2 partials (int-bit atomicMax, values >= 0)
// ---------------------------------------------------------------------------
__global__ void max_kernel(const float* __restrict__ c1, const float* __restrict__ c2) {
    int id = blockIdx.x;
    int t = id >> 6, b = (id >> 3) & 7, s = id & 7;
    const float* c = (t ? c2 : c1) + (size_t)b * 3 * NPTS + s * 4096;
    float mx = g_sum[t][b][0] * (1.0f / NPTS);
    float my = g_sum[t][b][1] * (1.0f / NPTS);
    float mz = g_sum[t][b][2] * (1.0f / NPTS);

    float best = 0.f;
    for (int n = threadIdx.x; n < 4096; n += 256) {
        float x = c[n] - mx, y = c[NPTS + n] - my, z = c[2 * NPTS + n] - mz;
        best = fmaxf(best, x * x + y * y + z * z);
    }
    #pragma unroll
    for (int off = 16; off; off >>= 1)
        best = fmaxf(best, __shfl_down_sync(0xffffffffu, best, off));
    __shared__ float red[8];
    int lane = threadIdx.x & 31, w = threadIdx.x >> 5;
    if (lane == 0) red[w] = best;
    __syncthreads();
    if (threadIdx.x == 0) {
        float m = 0.f;
        #pragma unroll
        for (int i = 0; i < 8; i++) m = fmaxf(m, red[i]);
        atomicMax(&g_max[t][b], __float_as_int(m));
    }
}

// ---------------------------------------------------------------------------
// Scatter one batch of x2 into fp16 grid. Vectorized transpose loads,
// 16B v4.f16x2 reds. 1024 blocks = one full wave.
// ---------------------------------------------------------------------------
__global__ void scatter_kernel(const float* __restrict__ x2f, const float* __restrict__ x2c,
                               int b) {
    int tile = blockIdx.x;
    int n0   = tile * 32;
    int tx = threadIdx.x, warp = tx >> 5, lane = tx & 31;

    __shared__ float smf[32][132];   // point-major; row stride 132 words (16B-multiple)
    __shared__ int   ssidx[32];      // voxel*CH element offset

    if (tx < 32) {
        int n = n0 + tx;
        const float* c = x2c + (size_t)b * 3 * NPTS;
        float inv = 0.5f / sqrtf(__int_as_float(g_max[1][b]));
        float mx = g_sum[1][b][0] * (1.0f / NPTS);
        float my = g_sum[1][b][1] * (1.0f / NPTS);
        float mz = g_sum[1][b][2] * (1.0f / NPTS);
        float fx = ((c[n]            - mx) * inv + 0.5f) * (float)RES;
        float fy = ((c[NPTS + n]     - my) * inv + 0.5f) * (float)RES;
        float fz = ((c[2 * NPTS + n] - mz) * inv + 0.5f) * (float)RES;
        int vx = (int)rintf(fminf(fmaxf(fx, 0.f), (float)(RES - 1)));
        int vy = (int)rintf(fminf(fmaxf(fy, 0.f), (float)(RES - 1)));
        int vz = (int)rintf(fminf(fmaxf(fz, 0.f), (float)(RES - 1)));
        int v = (vx * RES + vy) * RES + vz;
        ssidx[tx] = v * CH;
        atomicAdd(&g_cnt[b * R3 + v], 1.0f);
    }
    // vectorized transpose load: lane covers 4 consecutive points of channel c
    const float4* fb4 = (const float4*)(x2f + (size_t)b * CH * NPTS + n0);
    #pragma unroll
    for (int j = 0; j < 4; j++) {
        int c  = j * 32 + (warp << 2) + (lane >> 3);
        int p4 = lane & 7;
        float4 v = __ldcs(&fb4[(size_t)c * (NPTS / 4) + p4]);
        smf[4 * p4 + 0][c] = v.x;
        smf[4 * p4 + 1][c] = v.y;
        smf[4 * p4 + 2][c] = v.z;
        smf[4 * p4 + 3][c] = v.w;
    }
    __syncthreads();

    // per point: half-warp (16 lanes x 8ch) -> one 16B v4.f16x2 vector red
    __half* gb = g_gridh + (size_t)b * R3 * CH;
    #pragma unroll
    for (int i = 0; i < 2; i++) {
        int p = (warp << 2) | (i << 1) | (lane >> 4);   // 2 points per pass
        int g = lane & 15;                               // 8-channel group
        float4 va = *(const float4*)&smf[p][8 * g];
        float4 vb = *(const float4*)&smf[p][8 * g + 4];
        __half2 h0 = __floats2half2_rn(va.x, va.y);
        __half2 h1 = __floats2half2_rn(va.z, va.w);
        __half2 h2 = __floats2half2_rn(vb.x, vb.y);
        __half2 h3 = __floats2half2_rn(vb.z, vb.w);
        __half* gp = gb + ssidx[p] + 8 * g;
        asm volatile("red.global.add.noftz.v4.f16x2 [%0], {%1, %2, %3, %4};"
                     :: "l"(gp), "r"(*(unsigned*)&h0), "r"(*(unsigned*)&h1),
                        "r"(*(unsigned*)&h2), "r"(*(unsigned*)&h3)
                     : "memory");
    }
}

// ---------------------------------------------------------------------------
// Trilinear devoxelize one batch from fp16 sum-grid (cnt folded into weights).
// ---------------------------------------------------------------------------
__global__ void devox_kernel(const float* __restrict__ x1c, float* __restrict__ out, int b) {
    int tile = blockIdx.x;
    int n0   = tile * 32;
    int tx = threadIdx.x, warp = tx >> 5, lane = tx & 31;

    __shared__ float4 sm4[32][33];   // [point][col]; lane g stores cols g and 16+g
    __shared__ int    sidx[32][8];   // voxel*CH
    __shared__ float  sw[32][8];     // weight / max(cnt,1)

    // parallel setup: thread (p = tx&31, k = tx>>5) computes corner k of point p
    {
        int p = tx & 31, k = tx >> 5;
        int n = n0 + p;
        const float* c = x1c + (size_t)b * 3 * NPTS;
        float inv = 0.5f / sqrtf(__int_as_float(g_max[0][b]));
        float mx = g_sum[0][b][0] * (1.0f / NPTS);
        float my = g_sum[0][b][1] * (1.0f / NPTS);
        float mz = g_sum[0][b][2] * (1.0f / NPTS);
        float nc0 = fminf(fmaxf(((c[n]            - mx) * inv + 0.5f) * (float)RES, 0.f), (float)(RES - 1));
        float nc1 = fminf(fmaxf(((c[NPTS + n]     - my) * inv + 0.5f) * (float)RES, 0.f), (float)(RES - 1));
        float nc2 = fminf(fmaxf(((c[2 * NPTS + n] - mz) * inv + 0.5f) * (float)RES, 0.f), (float)(RES - 1));
        float f0 = floorf(nc0), f1 = floorf(nc1), f2 = floorf(nc2);
        int lx = (int)f0, ly = (int)f1, lz = (int)f2;
        float dx = nc0 - f0, dy = nc1 - f1, dz = nc2 - f2;
        int hx = min(lx + 1, RES - 1), hy = min(ly + 1, RES - 1), hz = min(lz + 1, RES - 1);
        int xi = (k & 4) ? hx : lx;
        int yi = (k & 2) ? hy : ly;
        int zi = (k & 1) ? hz : lz;
        float wgt = ((k & 4) ? dx : 1.f - dx) *
                    ((k & 2) ? dy : 1.f - dy) *
                    ((k & 1) ? dz : 1.f - dz);
        int v = (xi * RES + yi) * RES + zi;
        sidx[p][k] = v * CH;
        sw[p][k]   = wgt / fmaxf(g_cnt[b * R3 + v], 1.0f);
    }
    __syncthreads();

    // gather: half-warp per point, lane covers 8 consecutive channels (LDG.128)
    const __half* gb = g_gridh + (size_t)b * R3 * CH;
    #pragma unroll
    for (int i = 0; i < 2; i++) {
        int p = (warp << 2) | (i << 1) | (lane >> 4);
        int g = lane & 15;
        float a0 = 0.f, a1 = 0.f, a2 = 0.f, a3 = 0.f;
        float a4 = 0.f, a5 = 0.f, a6 = 0.f, a7 = 0.f;
        #pragma unroll
        for (int k = 0; k < 8; k++) {
            float wk = sw[p][k];
            uint4 u = *(const uint4*)(gb + sidx[p][k] + 8 * g);
            float2 q0 = __half22float2(*(__half2*)&u.x);
            float2 q1 = __half22float2(*(__half2*)&u.y);
            float2 q2 = __half22float2(*(__half2*)&u.z);
            float2 q3 = __half22float2(*(__half2*)&u.w);
            a0 = fmaf(wk, q0.x, a0); a1 = fmaf(wk, q0.y, a1);
            a2 = fmaf(wk, q1.x, a2); a3 = fmaf(wk, q1.y, a3);
            a4 = fmaf(wk, q2.x, a4); a5 = fmaf(wk, q2.y, a5);
            a6 = fmaf(wk, q3.x, a6); a7 = fmaf(wk, q3.y, a7);
        }
        sm4[p][g]      = make_float4(a0, a1, a2, a3);
        sm4[p][16 + g] = make_float4(a4, a5, a6, a7);
    }
    __syncthreads();

    // out: conflict-free LDS.128 per column, coalesced streaming STGs
    float* ob = out + ((size_t)b * 2 * CH + CH) * NPTS + n0;
    #pragma unroll
    for (int g2 = warp; g2 < 32; g2 += 8) {
        float4 f = sm4[lane][g2];                     // LDS.128 conflict-free
        int ch0 = (g2 < 16) ? 8 * g2 : 8 * (g2 - 16) + 4;
        __stcs(&ob[(size_t)(ch0 + 0) * NPTS + lane], f.x);
        __stcs(&ob[(size_t)(ch0 + 1) * NPTS + lane], f.y);
        __stcs(&ob[(size_t)(ch0 + 2) * NPTS + lane], f.z);
        __stcs(&ob[(size_t)(ch0 + 3) * NPTS + lane], f.w);
    }
}

// ---------------------------------------------------------------------------
// Multi-stream pipelined launch (fork/join via events; graph-capturable).
//   s0 (capture stream): stats -> scatter[b] (per batch, events)
//   s1: zero (|| stats) -> devox[b] as each scatter[b] completes
//   s2: x1 passthrough copy (independent, spans entire duration)
// ---------------------------------------------------------------------------
extern "C" void kernel_launch(void* const* d_in, const int* in_sizes, int n_in,
                              void* d_out, int out_size) {
    const float* x1f = (const float*)d_in[0];
    const float* x2f = (const float*)d_in[1];
    const float* x1c = (const float*)d_in[2];
    const float* x2c = (const float*)d_in[3];
    float* out = (float*)d_out;

    static cudaStream_t s1 = nullptr, s2 = nullptr;
    static cudaEvent_t eStart, eZero, eCopy, eSb[BATCH], eDevDone;
    if (!s1) {
        cudaStreamCreateWithFlags(&s1, cudaStreamNonBlocking);
        cudaStreamCreateWithFlags(&s2, cudaStreamNonBlocking);
        cudaEventCreateWithFlags(&eStart,   cudaEventDisableTiming);
        cudaEventCreateWithFlags(&eZero,    cudaEventDisableTiming);
        cudaEventCreateWithFlags(&eCopy,    cudaEventDisableTiming);
        cudaEventCreateWithFlags(&eDevDone, cudaEventDisableTiming);
        for (int b = 0; b < BATCH; b++)
            cudaEventCreateWithFlags(&eSb[b], cudaEventDisableTiming);
    }

    cudaEventRecord(eStart, 0);

    // s1: zero grid/cnt/stats accumulators (independent of mean/max)
    cudaStreamWaitEvent(s1, eStart, 0);
    zero_kernel<<<4096, 256, 0, s1>>>();
    cudaEventRecord(eZero, s1);

    // s2: fully independent x1 passthrough copy
    cudaStreamWaitEvent(s2, eStart, 0);
    copy_kernel<<<4096, 256, 0, s2>>>(x1f, out);
    cudaEventRecord(eCopy, s2);

    // s0: stats (writes g_sum/g_max AFTER zero? no - zero also clears them)
    // NOTE: mean/max accumulate into g_sum/g_max which zero_kernel clears ->
    // stats must wait for the zero of those 64 words. Order via eZero.
    cudaStreamWaitEvent(0, eZero, 0);
    mean_kernel<<<128, 256>>>(x1c, x2c);
    max_kernel<<<128, 256>>>(x1c, x2c);

    // s0: per-batch scatter, each records its completion event
    for (int b = 0; b < BATCH; b++) {
        scatter_kernel<<<NPTS / 32, 256>>>(x2f, x2c, b);
        cudaEventRecord(eSb[b], 0);
    }

    // s1: per-batch devox pipelined behind scatter
    for (int b = 0; b < BATCH; b++) {
        cudaStreamWaitEvent(s1, eSb[b], 0);
        devox_kernel<<<NPTS / 32, 256, 0, s1>>>(x1c, out, b);
    }
    cudaEventRecord(eDevDone, s1);

    // rejoin everything on the capture stream
    cudaStreamWaitEvent(0, eDevDone, 0);
    cudaStreamWaitEvent(0, eCopy, 0);
}

// round 9
// speedup vs baseline: 1.2690x; 1.2690x over previous
#include <cuda_runtime.h>
#include <cuda_fp16.h>

#define NPTS  32768
#define BATCH 8
#define CH    128
#define RES   32
#define R3    32768   // 32^3

// Scratch (device globals: no allocation allowed)
__device__ __half g_gridh[(size_t)BATCH * R3 * CH];   // fp16 scatter sums [b][v][c] (64 MB)
__device__ float  g_cnt  [BATCH * R3];
__device__ float  g_stats[2][BATCH][4];               // {mx,my,mz, 0.5/maxnorm} written directly

// ---------------------------------------------------------------------------
// Zero fp16 grid + counts (graph replays -> every launch). No stats here.
// ---------------------------------------------------------------------------
__global__ void zero_kernel() {
    const size_t gtotal = (size_t)BATCH * R3 * CH * 2 / 16;   // 4M float4
    float4* p = (float4*)g_gridh;
    size_t stride = (size_t)gridDim.x * blockDim.x;
    for (size_t i = (size_t)blockIdx.x * blockDim.x + threadIdx.x; i < gtotal; i += stride)
        p[i] = make_float4(0.f, 0.f, 0.f, 0.f);
    const size_t ctotal = (size_t)BATCH * R3 / 4;
    float4* q = (float4*)g_cnt;
    for (size_t i = (size_t)blockIdx.x * blockDim.x + threadIdx.x; i < ctotal; i += stride)
        q[i] = make_float4(0.f, 0.f, 0.f, 0.f);
}

// ---------------------------------------------------------------------------
// Fused per-(tensor,batch) stats: mean then max||c-mean||^2 (2nd pass L2-hot).
// 16 blocks x 1024 threads; writes g_stats directly (no atomics, no pre-zero).
// ---------------------------------------------------------------------------
__global__ void stats_kernel(const float* __restrict__ c1, const float* __restrict__ c2) {
    int t = blockIdx.x >> 3, b = blockIdx.x & 7;
    const float4* c = (const float4*)((t ? c2 : c1) + (size_t)b * 3 * NPTS);
    const int ROW4 = NPTS / 4;   // 8192 float4 per coordinate row
    int tx = threadIdx.x, lane = tx & 31, w = tx >> 5;

    __shared__ float red[3][32];
    __shared__ float smean[3];

    // pass 1: sums
    float s0 = 0.f, s1 = 0.f, s2 = 0.f;
    for (int i = tx; i < ROW4; i += 1024) {
        float4 v0 = c[i];
        float4 v1 = c[ROW4 + i];
        float4 v2 = c[2 * ROW4 + i];
        s0 += (v0.x + v0.y) + (v0.z + v0.w);
        s1 += (v1.x + v1.y) + (v1.z + v1.w);
        s2 += (v2.x + v2.y) + (v2.z + v2.w);
    }
    #pragma unroll
    for (int off = 16; off; off >>= 1) {
        s0 += __shfl_down_sync(0xffffffffu, s0, off);
        s1 += __shfl_down_sync(0xffffffffu, s1, off);
        s2 += __shfl_down_sync(0xffffffffu, s2, off);
    }
    if (lane == 0) { red[0][w] = s0; red[1][w] = s1; red[2][w] = s2; }
    __syncthreads();
    if (w == 0) {
        float a0 = red[0][lane], a1 = red[1][lane], a2 = red[2][lane];
        #pragma unroll
        for (int off = 16; off; off >>= 1) {
            a0 += __shfl_down_sync(0xffffffffu, a0, off);
            a1 += __shfl_down_sync(0xffffffffu, a1, off);
            a2 += __shfl_down_sync(0xffffffffu, a2, off);
        }
        if (lane == 0) {
            smean[0] = a0 * (1.0f / NPTS);
            smean[1] = a1 * (1.0f / NPTS);
            smean[2] = a2 * (1.0f / NPTS);
        }
    }
    __syncthreads();
    float mx = smean[0], my = smean[1], mz = smean[2];

    // pass 2: max norm^2 (data L2-resident)
    float best = 0.f;
    for (int i = tx; i < ROW4; i += 1024) {
        float4 v0 = c[i];
        float4 v1 = c[ROW4 + i];
        float4 v2 = c[2 * ROW4 + i];
        float x, y, z;
        x = v0.x - mx; y = v1.x - my; z = v2.x - mz; best = fmaxf(best, x*x + y*y + z*z);
        x = v0.y - mx; y = v1.y - my; z = v2.y - mz; best = fmaxf(best, x*x + y*y + z*z);
        x = v0.z - mx; y = v1.z - my; z = v2.z - mz; best = fmaxf(best, x*x + y*y + z*z);
        x = v0.w - mx; y = v1.w - my; z = v2.w - mz; best = fmaxf(best, x*x + y*y + z*z);
    }
    #pragma unroll
    for (int off = 16; off; off >>= 1)
        best = fmaxf(best, __shfl_down_sync(0xffffffffu, best, off));
    if (lane == 0) red[0][w] = best;
    __syncthreads();
    if (tx == 0) {
        float m = 0.f;
        #pragma unroll
        for (int i = 0; i < 32; i++) m = fmaxf(m, red[0][i]);
        g_stats[t][b][0] = mx;
        g_stats[t][b][1] = my;
        g_stats[t][b][2] = mz;
        g_stats[t][b][3] = 0.5f / sqrtf(m);
    }
}

// ---------------------------------------------------------------------------
// Independent x1 -> out[:, 0:128, :] passthrough copy (flat float4 stream).
// Runs concurrent with stats/zero/scatter (those phases have L2+DRAM headroom).
// ---------------------------------------------------------------------------
__global__ void copy_kernel(const float* __restrict__ x1f, float* __restrict__ out) {
    const float4* src = (const float4*)x1f;
    const size_t nvec = (size_t)BATCH * CH * NPTS / 4;   // 16M float4
    size_t stride = (size_t)gridDim.x * blockDim.x;
    for (size_t i = (size_t)blockIdx.x * blockDim.x + threadIdx.x; i < nvec; i += stride) {
        size_t e = i * 4;
        size_t bb = e >> 22;                              // CH*NPTS = 2^22
        float4 v = __ldcs(&src[i]);
        __stcs((float4*)(out + e + (bb << 22)), v);
    }
}

// ---------------------------------------------------------------------------
// Scatter x2 -> fp16 grid. Vectorized transpose loads, 16B v4.f16x2 reds.
// ---------------------------------------------------------------------------
__global__ void scatter_kernel(const float* __restrict__ x2f, const float* __restrict__ x2c) {
    int b    = blockIdx.x >> 10;
    int tile = blockIdx.x & 1023;
    int n0   = tile * 32;
    int tx = threadIdx.x, warp = tx >> 5, lane = tx & 31;

    __shared__ float smf[32][132];   // point-major; row stride 132 words (16B-multiple)
    __shared__ int   ssidx[32];      // voxel*CH element offset

    if (tx < 32) {
        int n = n0 + tx;
        const float* c = x2c + (size_t)b * 3 * NPTS;
        float inv = g_stats[1][b][3];
        float mx = g_stats[1][b][0], my = g_stats[1][b][1], mz = g_stats[1][b][2];
        float fx = ((c[n]            - mx) * inv + 0.5f) * (float)RES;
        float fy = ((c[NPTS + n]     - my) * inv + 0.5f) * (float)RES;
        float fz = ((c[2 * NPTS + n] - mz) * inv + 0.5f) * (float)RES;
        int vx = (int)rintf(fminf(fmaxf(fx, 0.f), (float)(RES - 1)));
        int vy = (int)rintf(fminf(fmaxf(fy, 0.f), (float)(RES - 1)));
        int vz = (int)rintf(fminf(fmaxf(fz, 0.f), (float)(RES - 1)));
        int v = (vx * RES + vy) * RES + vz;
        ssidx[tx] = v * CH;
        atomicAdd(&g_cnt[b * R3 + v], 1.0f);
    }
    // vectorized transpose load: lane covers 4 consecutive points of channel c
    const float4* fb4 = (const float4*)(x2f + (size_t)b * CH * NPTS + n0);
    #pragma unroll
    for (int j = 0; j < 4; j++) {
        int c  = j * 32 + (warp << 2) + (lane >> 3);
        int p4 = lane & 7;
        float4 v = __ldcs(&fb4[(size_t)c * (NPTS / 4) + p4]);
        smf[4 * p4 + 0][c] = v.x;
        smf[4 * p4 + 1][c] = v.y;
        smf[4 * p4 + 2][c] = v.z;
        smf[4 * p4 + 3][c] = v.w;
    }
    __syncthreads();

    // per point: half-warp (16 lanes x 8ch) -> one 16B v4.f16x2 vector red
    __half* gb = g_gridh + (size_t)b * R3 * CH;
    #pragma unroll
    for (int i = 0; i < 2; i++) {
        int p = (warp << 2) | (i << 1) | (lane >> 4);   // 2 points per pass
        int g = lane & 15;                               // 8-channel group
        float4 va = *(const float4*)&smf[p][8 * g];
        float4 vb = *(const float4*)&smf[p][8 * g + 4];
        __half2 h0 = __floats2half2_rn(va.x, va.y);
        __half2 h1 = __floats2half2_rn(va.z, va.w);
        __half2 h2 = __floats2half2_rn(vb.x, vb.y);
        __half2 h3 = __floats2half2_rn(vb.z, vb.w);
        __half* gp = gb + ssidx[p] + 8 * g;
        asm volatile("red.global.add.noftz.v4.f16x2 [%0], {%1, %2, %3, %4};"
                     :: "l"(gp), "r"(*(unsigned*)&h0), "r"(*(unsigned*)&h1),
                        "r"(*(unsigned*)&h2), "r"(*(unsigned*)&h3)
                     : "memory");
    }
}

// ---------------------------------------------------------------------------
// Trilinear devoxelize from fp16 sum-grid (cnt folded into corner weights).
// Pure gather + out[:,128:256,:] write; copy lives on another stream.
// ---------------------------------------------------------------------------
__global__ void devox_kernel(const float* __restrict__ x1c, float* __restrict__ out) {
    int b    = blockIdx.x >> 10;
    int tile = blockIdx.x & 1023;
    int n0   = tile * 32;
    int tx = threadIdx.x, warp = tx >> 5, lane = tx & 31;

    __shared__ float4 sm4[32][33];   // [point][col]; lane g stores cols g and 16+g
    __shared__ int    sidx[32][8];   // voxel*CH
    __shared__ float  sw[32][8];     // weight / max(cnt,1)

    // parallel setup: thread (p = tx&31, k = tx>>5) computes corner k of point p
    {
        int p = tx & 31, k = tx >> 5;
        int n = n0 + p;
        const float* c = x1c + (size_t)b * 3 * NPTS;
        float inv = g_stats[0][b][3];
        float mx = g_stats[0][b][0], my = g_stats[0][b][1], mz = g_stats[0][b][2];
        float nc0 = fminf(fmaxf(((c[n]            - mx) * inv + 0.5f) * (float)RES, 0.f), (float)(RES - 1));
        float nc1 = fminf(fmaxf(((c[NPTS + n]     - my) * inv + 0.5f) * (float)RES, 0.f), (float)(RES - 1));
        float nc2 = fminf(fmaxf(((c[2 * NPTS + n] - mz) * inv + 0.5f) * (float)RES, 0.f), (float)(RES - 1));
        float f0 = floorf(nc0), f1 = floorf(nc1), f2 = floorf(nc2);
        int lx = (int)f0, ly = (int)f1, lz = (int)f2;
        float dx = nc0 - f0, dy = nc1 - f1, dz = nc2 - f2;
        int hx = min(lx + 1, RES - 1), hy = min(ly + 1, RES - 1), hz = min(lz + 1, RES - 1);
        int xi = (k & 4) ? hx : lx;
        int yi = (k & 2) ? hy : ly;
        int zi = (k & 1) ? hz : lz;
        float wgt = ((k & 4) ? dx : 1.f - dx) *
                    ((k & 2) ? dy : 1.f - dy) *
                    ((k & 1) ? dz : 1.f - dz);
        int v = (xi * RES + yi) * RES + zi;
        sidx[p][k] = v * CH;
        sw[p][k]   = wgt / fmaxf(g_cnt[b * R3 + v], 1.0f);
    }
    __syncthreads();

    // gather: half-warp per point, lane covers 8 consecutive channels (LDG.128)
    const __half* gb = g_gridh + (size_t)b * R3 * CH;
    #pragma unroll
    for (int i = 0; i < 2; i++) {
        int p = (warp << 2) | (i << 1) | (lane >> 4);
        int g = lane & 15;
        float a0 = 0.f, a1 = 0.f, a2 = 0.f, a3 = 0.f;
        float a4 = 0.f, a5 = 0.f, a6 = 0.f, a7 = 0.f;
        #pragma unroll
        for (int k = 0; k < 8; k++) {
            float wk = sw[p][k];
            uint4 u = *(const uint4*)(gb + sidx[p][k] + 8 * g);
            float2 q0 = __half22float2(*(__half2*)&u.x);
            float2 q1 = __half22float2(*(__half2*)&u.y);
            float2 q2 = __half22float2(*(__half2*)&u.z);
            float2 q3 = __half22float2(*(__half2*)&u.w);
            a0 = fmaf(wk, q0.x, a0); a1 = fmaf(wk, q0.y, a1);
            a2 = fmaf(wk, q1.x, a2); a3 = fmaf(wk, q1.y, a3);
            a4 = fmaf(wk, q2.x, a4); a5 = fmaf(wk, q2.y, a5);
            a6 = fmaf(wk, q3.x, a6); a7 = fmaf(wk, q3.y, a7);
        }
        sm4[p][g]      = make_float4(a0, a1, a2, a3);
        sm4[p][16 + g] = make_float4(a4, a5, a6, a7);
    }
    __syncthreads();

    // out: conflict-free LDS.128 per column, coalesced streaming STGs
    float* ob = out + ((size_t)b * 2 * CH + CH) * NPTS + n0;
    #pragma unroll
    for (int g2 = warp; g2 < 32; g2 += 8) {
        float4 f = sm4[lane][g2];                     // LDS.128 conflict-free
        int ch0 = (g2 < 16) ? 8 * g2 : 8 * (g2 - 16) + 4;
        __stcs(&ob[(size_t)(ch0 + 0) * NPTS + lane], f.x);
        __stcs(&ob[(size_t)(ch0 + 1) * NPTS + lane], f.y);
        __stcs(&ob[(size_t)(ch0 + 2) * NPTS + lane], f.z);
        __stcs(&ob[(size_t)(ch0 + 3) * NPTS + lane], f.w);
    }
}

// ---------------------------------------------------------------------------
// Launch topology (graph-capturable fork/join):
//   s0: stats (16x1024)  -> join(eZero) -> scatter(8192) -> devox(8192)
//   s1: zero  (|| stats)
//   s2: copy  (|| stats/zero/scatter; independent out region)
// ---------------------------------------------------------------------------
extern "C" void kernel_launch(void* const* d_in, const int* in_sizes, int n_in,
                              void* d_out, int out_size) {
    const float* x1f = (const float*)d_in[0];
    const float* x2f = (const float*)d_in[1];
    const float* x1c = (const float*)d_in[2];
    const float* x2c = (const float*)d_in[3];
    float* out = (float*)d_out;

    static cudaStream_t s1 = nullptr, s2 = nullptr;
    static cudaEvent_t eStart, eZero, eCopy;
    if (!s1) {
        cudaStreamCreateWithFlags(&s1, cudaStreamNonBlocking);
        cudaStreamCreateWithFlags(&s2, cudaStreamNonBlocking);
        cudaEventCreateWithFlags(&eStart, cudaEventDisableTiming);
        cudaEventCreateWithFlags(&eZero,  cudaEventDisableTiming);
        cudaEventCreateWithFlags(&eCopy,  cudaEventDisableTiming);
    }

    cudaEventRecord(eStart, 0);

    // s1: zero grid + counts (independent of stats)
    cudaStreamWaitEvent(s1, eStart, 0);
    zero_kernel<<<4096, 256, 0, s1>>>();
    cudaEventRecord(eZero, s1);

    // s2: independent x1 passthrough copy (distinct out region)
    cudaStreamWaitEvent(s2, eStart, 0);
    copy_kernel<<<4096, 256, 0, s2>>>(x1f, out);
    cudaEventRecord(eCopy, s2);

    // s0: fused stats (no dependency on zero), then scatter + devox
    stats_kernel<<<16, 1024>>>(x1c, x2c);
    cudaStreamWaitEvent(0, eZero, 0);
    scatter_kernel<<<BATCH * (NPTS / 32), 256>>>(x2f, x2c);
    devox_kernel<<<BATCH * (NPTS / 32), 256>>>(x1c, out);

    // rejoin copy on the capture stream
    cudaStreamWaitEvent(0, eCopy, 0);
}